// round 4
// baseline (speedup 1.0000x reference)
#include <cuda_runtime.h>

#define Bb 2
#define Nn 2048
#define Dd 1024
#define Hh 16
#define HD 64

// Scratch (static device arrays -- no allocation allowed)
__device__ __align__(16) float g_q   [Bb*Hh*Nn*HD];   // [bh][n][hd]
__device__ __align__(16) float g_k   [Bb*Hh*Nn*HD];   // [bh][n][hd]
__device__ __align__(16) float g_vt  [Bb*Hh*HD*Nn];   // [bh][hd][n]
__device__ __align__(16) float g_attn[Bb*Nn*Dd];      // [B*N, D]

// ---------------------------------------------------------------------------
__device__ __forceinline__ unsigned f2tf(float f) {
    unsigned u; asm("cvt.rna.tf32.f32 %0, %1;" : "=r"(u) : "f"(f)); return u;
}
__device__ __forceinline__ void mma_tf32(float* d, const unsigned* a, const unsigned* b) {
    asm("mma.sync.aligned.m16n8k8.row.col.f32.tf32.tf32.f32 "
        "{%0,%1,%2,%3},{%4,%5,%6,%7},{%8,%9},{%0,%1,%2,%3};"
        : "+f"(d[0]), "+f"(d[1]), "+f"(d[2]), "+f"(d[3])
        : "r"(a[0]), "r"(a[1]), "r"(a[2]), "r"(a[3]), "r"(b[0]), "r"(b[1]));
}
__device__ __forceinline__ void cp_async16(void* smem, const void* gmem) {
    unsigned s = (unsigned)__cvta_generic_to_shared(smem);
    asm volatile("cp.async.cg.shared.global [%0], [%1], 16;" :: "r"(s), "l"(gmem));
}
#define CP_COMMIT() asm volatile("cp.async.commit_group;")
#define CP_WAIT0()  asm volatile("cp.async.wait_group 0;")

// ---------------------------------------------------------------------------
// TF32 GEMM 128x128x32, 256 threads, double-buffered cp.async pipeline.
// smem holds raw fp32; cvt to tf32 at fragment load.
// EPI==0: C = x @ w_qkv + b -> scattered q/k/vt.  EPI==1: g_attn @ w_proj -> Cout.
// ---------------------------------------------------------------------------
#define GEMM_SMEM (2*128*36*4 + 2*32*136*4)   // 36864 + 34816 = 71680

template<int NCOLS, int EPI>
__global__ void __launch_bounds__(256, 2)
gemm_tf32(const float* __restrict__ A, const float* __restrict__ B,
          const float* __restrict__ bias, float* __restrict__ Cout)
{
    extern __shared__ char smem[];
    float (*As)[128][36] = (float(*)[128][36])smem;              // [2][128][36]
    float (*Bs)[32][136] = (float(*)[32][136])(smem + 36864);    // [2][32][136]

    const int t  = threadIdx.x;
    const int w  = t >> 5;
    const int ln = t & 31;
    const int g  = ln >> 2;
    const int c  = ln & 3;
    const int wm = (w >> 2) * 64;
    const int wn = (w & 3) * 32;
    const int m0 = blockIdx.y * 128;
    const int n0 = blockIdx.x * 128;

    const float* Ap = (EPI == 1) ? g_attn : A;

    float acc[4][4][4];
    #pragma unroll
    for (int mt = 0; mt < 4; mt++)
        #pragma unroll
        for (int nt = 0; nt < 4; nt++)
            #pragma unroll
            for (int i = 0; i < 4; i++) acc[mt][nt][i] = 0.f;

    // tile loader: stage st, k offset k0
    auto load_tiles = [&](int st, int k0) {
        #pragma unroll
        for (int s = 0; s < 4; s++) {
            int q = t + s * 256;                    // 1024 16B chunks (A)
            int row = q >> 3, col = (q & 7) * 4;
            cp_async16(&As[st][row][col],
                       Ap + (size_t)(m0 + row) * 1024 + k0 + col);
        }
        #pragma unroll
        for (int s = 0; s < 4; s++) {
            int q = t + s * 256;                    // 1024 16B chunks (B)
            int row = q >> 5, col = (q & 31) * 4;
            cp_async16(&Bs[st][row][col],
                       B + (size_t)(k0 + row) * NCOLS + n0 + col);
        }
    };

    load_tiles(0, 0);
    CP_COMMIT(); CP_WAIT0();
    __syncthreads();

    for (int it = 0; it < 32; it++) {
        int cur = it & 1;
        if (it < 31) { load_tiles(cur ^ 1, (it + 1) * 32); CP_COMMIT(); }

        #pragma unroll
        for (int kk = 0; kk < 32; kk += 8) {
            unsigned af[4][4], bf[4][2];
            #pragma unroll
            for (int mt = 0; mt < 4; mt++) {
                int r = wm + mt * 16;
                af[mt][0] = f2tf(As[cur][r + g    ][kk + c]);
                af[mt][1] = f2tf(As[cur][r + g + 8][kk + c]);
                af[mt][2] = f2tf(As[cur][r + g    ][kk + c + 4]);
                af[mt][3] = f2tf(As[cur][r + g + 8][kk + c + 4]);
            }
            #pragma unroll
            for (int nt = 0; nt < 4; nt++) {
                int cc = wn + nt * 8 + g;
                bf[nt][0] = f2tf(Bs[cur][kk + c    ][cc]);
                bf[nt][1] = f2tf(Bs[cur][kk + c + 4][cc]);
            }
            #pragma unroll
            for (int mt = 0; mt < 4; mt++)
                #pragma unroll
                for (int nt = 0; nt < 4; nt++)
                    mma_tf32(acc[mt][nt], af[mt], bf[nt]);
        }

        if (it < 31) { CP_WAIT0(); __syncthreads(); }
    }

    // Epilogue
    float bv[4][2];
    #pragma unroll
    for (int nt = 0; nt < 4; nt++) {
        int col = n0 + wn + nt * 8 + 2 * c;
        bv[nt][0] = __ldg(bias + col);
        bv[nt][1] = __ldg(bias + col + 1);
    }
    #pragma unroll
    for (int mt = 0; mt < 4; mt++) {
        #pragma unroll
        for (int half = 0; half < 2; half++) {
            int r = m0 + wm + mt * 16 + g + half * 8;
            #pragma unroll
            for (int nt = 0; nt < 4; nt++) {
                int col = n0 + wn + nt * 8 + 2 * c;
                float v0 = acc[mt][nt][half * 2 + 0] + bv[nt][0];
                float v1 = acc[mt][nt][half * 2 + 1] + bv[nt][1];
                if (EPI == 0) {
                    int b = r >> 11, n = r & 2047;
                    #pragma unroll
                    for (int e = 0; e < 2; e++) {
                        int cc = col + e;
                        float v = e ? v1 : v0;
                        int tt = cc >> 10, rem = cc & 1023;
                        int h = rem >> 6, d = rem & 63;
                        int bh = b * Hh + h;
                        if (tt == 0)      g_q [((size_t)(bh * Nn + n) << 6) + d] = v;
                        else if (tt == 1) g_k [((size_t)(bh * Nn + n) << 6) + d] = v;
                        else              g_vt[((size_t)(bh * HD + d) << 11) + n] = v;
                    }
                } else {
                    *(float2*)(Cout + (size_t)r * 1024 + col) = make_float2(v0, v1);
                }
            }
        }
    }
}

// ---------------------------------------------------------------------------
// Flash attention, TF32, double-buffered cp.async K/V, separate P buffer.
// 128 threads (4 warps), 64-query tile; 1 block barrier per k-tile.
// ---------------------------------------------------------------------------
#define ATTN_SMEM (2*64*68*4 + 2*64*68*4 + 64*68*4)   // 34816+34816+17408 = 87040

__global__ void __launch_bounds__(128)
attn_tf32(const float* __restrict__ bias)
{
    extern __shared__ char smem[];
    float    (*Kb)[64][68] = (float(*)[64][68])smem;              // raw fp32 K [key][d]
    float    (*Vb)[64][68] = (float(*)[64][68])(smem + 34816);    // raw fp32 V^T [d][key]
    unsigned (*Pb)[68]     = (unsigned(*)[68])(smem + 69632);     // tf32 P [q][key]

    const int t  = threadIdx.x;
    const int w  = t >> 5;
    const int ln = t & 31;
    const int g  = ln >> 2;
    const int c  = ln & 3;
    const int wq = w * 16;
    const int bh = blockIdx.y;
    const int b  = bh >> 4;
    const int h  = bh & 15;
    const int q0 = blockIdx.x * 64;

    const float* qp  = g_q  + ((size_t)bh * Nn) * HD;
    const float* kp  = g_k  + ((size_t)bh * Nn) * HD;
    const float* vtp = g_vt + ((size_t)bh * HD) * Nn;
    const float* bp  = bias + b * Nn;

    auto load_kv = [&](int st, int k0) {
        #pragma unroll
        for (int s = 0; s < 8; s++) {
            int q = t + s * 128;                   // 1024 chunks each
            int row = q >> 4, col = (q & 15) * 4;
            cp_async16(&Kb[st][row][col], kp + (size_t)(k0 + row) * HD + col);
            cp_async16(&Vb[st][row][col], vtp + (size_t)row * Nn + k0 + col);
        }
    };

    // Issue tile 0 loads, stage Q through Pb meanwhile
    load_kv(0, 0);
    CP_COMMIT();
    #pragma unroll
    for (int s = 0; s < 8; s++) {
        int idx = t + s * 128;
        int row = idx >> 4, col = (idx & 15) * 4;
        float4 v = *(const float4*)(qp + (size_t)(q0 + row) * HD + col);
        *(uint4*)&Pb[row][col] =
            make_uint4(f2tf(v.x), f2tf(v.y), f2tf(v.z), f2tf(v.w));
    }
    CP_WAIT0();
    __syncthreads();

    unsigned qf[8][4];
    #pragma unroll
    for (int kk = 0; kk < 8; kk++) {
        qf[kk][0] = Pb[wq + g    ][kk * 8 + c];
        qf[kk][1] = Pb[wq + g + 8][kk * 8 + c];
        qf[kk][2] = Pb[wq + g    ][kk * 8 + c + 4];
        qf[kk][3] = Pb[wq + g + 8][kk * 8 + c + 4];
    }

    float oacc[8][4];
    #pragma unroll
    for (int dn = 0; dn < 8; dn++)
        #pragma unroll
        for (int i = 0; i < 4; i++) oacc[dn][i] = 0.f;
    float m[2] = {-1e30f, -1e30f};
    float l[2] = {0.f, 0.f};

    for (int it = 0; it < Nn / 64; it++) {
        int cur = it & 1;
        int k0  = it * 64;
        if (it < Nn / 64 - 1) { load_kv(cur ^ 1, k0 + 64); CP_COMMIT(); }

        // S = Q @ K^T
        float sacc[8][4];
        #pragma unroll
        for (int nt = 0; nt < 8; nt++)
            #pragma unroll
            for (int i = 0; i < 4; i++) sacc[nt][i] = 0.f;

        #pragma unroll
        for (int kk = 0; kk < 8; kk++) {
            unsigned bf[8][2];
            #pragma unroll
            for (int nt = 0; nt < 8; nt++) {
                bf[nt][0] = f2tf(Kb[cur][nt * 8 + g][kk * 8 + c]);
                bf[nt][1] = f2tf(Kb[cur][nt * 8 + g][kk * 8 + c + 4]);
            }
            #pragma unroll
            for (int nt = 0; nt < 8; nt++)
                mma_tf32(sacc[nt], qf[kk], bf[nt]);
        }

        // scale + bias
        #pragma unroll
        for (int nt = 0; nt < 8; nt++) {
            int col = k0 + nt * 8 + 2 * c;
            float b0 = __ldg(bp + col), b1 = __ldg(bp + col + 1);
            sacc[nt][0] = sacc[nt][0] * 0.125f + b0;
            sacc[nt][1] = sacc[nt][1] * 0.125f + b1;
            sacc[nt][2] = sacc[nt][2] * 0.125f + b0;
            sacc[nt][3] = sacc[nt][3] * 0.125f + b1;
        }

        // Online softmax
        #pragma unroll
        for (int r = 0; r < 2; r++) {
            float mx = -1e30f;
            #pragma unroll
            for (int nt = 0; nt < 8; nt++)
                mx = fmaxf(mx, fmaxf(sacc[nt][2 * r], sacc[nt][2 * r + 1]));
            mx = fmaxf(mx, __shfl_xor_sync(0xffffffffu, mx, 1));
            mx = fmaxf(mx, __shfl_xor_sync(0xffffffffu, mx, 2));
            float mnew = fmaxf(m[r], mx);
            float sc = __expf(m[r] - mnew);
            m[r] = mnew;
            float su = 0.f;
            #pragma unroll
            for (int nt = 0; nt < 8; nt++) {
                float p0 = __expf(sacc[nt][2 * r]     - mnew);
                float p1 = __expf(sacc[nt][2 * r + 1] - mnew);
                sacc[nt][2 * r] = p0; sacc[nt][2 * r + 1] = p1;
                su += p0 + p1;
            }
            su += __shfl_xor_sync(0xffffffffu, su, 1);
            su += __shfl_xor_sync(0xffffffffu, su, 2);
            l[r] = l[r] * sc + su;
            #pragma unroll
            for (int dn = 0; dn < 8; dn++) {
                oacc[dn][2 * r]     *= sc;
                oacc[dn][2 * r + 1] *= sc;
            }
        }

        // P into warp-private rows of Pb (no block barrier needed)
        #pragma unroll
        for (int nt = 0; nt < 8; nt++) {
            int col = nt * 8 + 2 * c;
            Pb[wq + g    ][col    ] = f2tf(sacc[nt][0]);
            Pb[wq + g    ][col + 1] = f2tf(sacc[nt][1]);
            Pb[wq + g + 8][col    ] = f2tf(sacc[nt][2]);
            Pb[wq + g + 8][col + 1] = f2tf(sacc[nt][3]);
        }
        __syncwarp();

        // O += P @ V
        #pragma unroll
        for (int kk = 0; kk < 8; kk++) {
            unsigned pa[4];
            pa[0] = Pb[wq + g    ][kk * 8 + c];
            pa[1] = Pb[wq + g + 8][kk * 8 + c];
            pa[2] = Pb[wq + g    ][kk * 8 + c + 4];
            pa[3] = Pb[wq + g + 8][kk * 8 + c + 4];
            #pragma unroll
            for (int dn = 0; dn < 8; dn++) {
                unsigned vb[2];
                vb[0] = f2tf(Vb[cur][dn * 8 + g][kk * 8 + c]);
                vb[1] = f2tf(Vb[cur][dn * 8 + g][kk * 8 + c + 4]);
                mma_tf32(oacc[dn], pa, vb);
            }
        }

        if (it < Nn / 64 - 1) { CP_WAIT0(); __syncthreads(); }
    }

    // Finalize
    float inv[2] = {1.f / l[0], 1.f / l[1]};
    #pragma unroll
    for (int r = 0; r < 2; r++) {
        int n = q0 + wq + g + r * 8;
        float* outp = g_attn + ((size_t)(b * Nn + n)) * Dd + h * HD;
        #pragma unroll
        for (int dn = 0; dn < 8; dn++) {
            int col = dn * 8 + 2 * c;
            *(float2*)(outp + col) = make_float2(oacc[dn][2 * r] * inv[r],
                                                 oacc[dn][2 * r + 1] * inv[r]);
        }
    }
}

// ---------------------------------------------------------------------------
static const float* ptr_by_size(void* const* d_in, const int* in_sizes,
                                int n_in, int sz)
{
    for (int i = 0; i < n_in; i++)
        if (in_sizes[i] == sz) return (const float*)d_in[i];
    return nullptr;
}

extern "C" void kernel_launch(void* const* d_in, const int* in_sizes, int n_in,
                              void* d_out, int out_size)
{
    const float* x      = ptr_by_size(d_in, in_sizes, n_in, Bb * Nn * Dd);
    const float* abias  = ptr_by_size(d_in, in_sizes, n_in, Bb * Nn);
    const float* w_qkv  = ptr_by_size(d_in, in_sizes, n_in, Dd * 3 * Dd);
    const float* b_qkv  = ptr_by_size(d_in, in_sizes, n_in, 3 * Dd);
    const float* w_proj = ptr_by_size(d_in, in_sizes, n_in, Dd * Dd);
    const float* b_proj = ptr_by_size(d_in, in_sizes, n_in, Dd);
    float* out = (float*)d_out;

    cudaFuncSetAttribute(gemm_tf32<3 * Dd, 0>,
                         cudaFuncAttributeMaxDynamicSharedMemorySize, GEMM_SMEM);
    cudaFuncSetAttribute(gemm_tf32<Dd, 1>,
                         cudaFuncAttributeMaxDynamicSharedMemorySize, GEMM_SMEM);
    cudaFuncSetAttribute(attn_tf32,
                         cudaFuncAttributeMaxDynamicSharedMemorySize, ATTN_SMEM);

    gemm_tf32<3 * Dd, 0><<<dim3(24, 32), 256, GEMM_SMEM>>>(x, w_qkv, b_qkv, nullptr);
    attn_tf32<<<dim3(Nn / 64, Bb * Hh), 128, ATTN_SMEM>>>(abias);
    gemm_tf32<Dd, 1><<<dim3(8, 32), 256, GEMM_SMEM>>>(nullptr, w_proj, b_proj, out);
}